// round 3
// baseline (speedup 1.0000x reference)
#include <cuda_runtime.h>
#include <math.h>

#define B_SZ   32
#define D_IN   2
#define L_SEQ  4096
#define H_DIM  128
#define NL     6
#define NC     32
#define D_OUT  2
#define NSEQ   (B_SZ * H_DIM)        // 4096
#define CHUNKS 8
#define CHLEN  (L_SEQ / CHUNKS)      // 512
#define SPT    8                     // states per thread (4 threads per seq-chunk)
#define NG     (SPT / 2)             // packed f32x2 groups per thread = 4
#define LT2    32                    // l-tile for GLU kernel

typedef unsigned long long u64;

// ---------------- f32x2 helpers (sm_103a packed FMA) ----------------
__device__ __forceinline__ u64 pk(float lo, float hi) {
    u64 r;
    asm("mov.b64 %0, {%1, %2};" : "=l"(r) : "r"(__float_as_uint(lo)), "r"(__float_as_uint(hi)));
    return r;
}
__device__ __forceinline__ void upk(u64 a, float& lo, float& hi) {
    unsigned int x, y;
    asm("mov.b64 {%0, %1}, %2;" : "=r"(x), "=r"(y) : "l"(a));
    lo = __uint_as_float(x); hi = __uint_as_float(y);
}
__device__ __forceinline__ u64 fma2(u64 a, u64 b, u64 c) {
    u64 d;
    asm("fma.rn.f32x2 %0, %1, %2, %3;" : "=l"(d) : "l"(a), "l"(b), "l"(c));
    return d;
}
__device__ __forceinline__ u64 mul2(u64 a, u64 b) {
    u64 d;
    asm("mul.rn.f32x2 %0, %1, %2;" : "=l"(d) : "l"(a), "l"(b));
    return d;
}

// ---------------- scratch (static device arrays; no allocation) ----------------
__device__ float  g_h[NSEQ * L_SEQ];                 // current activations (B,H,L)
__device__ float  g_y[NSEQ * L_SEQ];                 // SSM output post-gelu (B,H,L)
__device__ float2 g_E[NSEQ * (CHUNKS - 1) * NC];     // chunk-end states
__device__ float  g_par[NL * 6 * H_DIM * NC];        // wre,wim,c2re,c2im,wpre,wpim
__device__ float  g_Wd[NL * 64 * H_DIM * 8];         // duplicated weights [l][o64][k][8]
__device__ float  g_pooled[NSEQ];

// ---------------- per-layer parameter precompute (double for accuracy) ----------
__global__ void param_kernel(const float* __restrict__ log_dt,
                             const float* __restrict__ C_re,
                             const float* __restrict__ C_im,
                             const float* __restrict__ log_A_real,
                             const float* __restrict__ A_imag) {
    int t = blockIdx.x * blockDim.x + threadIdx.x;
    if (t >= NL * H_DIM * NC) return;
    int layer = t / (H_DIM * NC);
    int hn    = t % (H_DIM * NC);
    int h     = hn / NC;

    double dt  = exp((double)log_dt[layer * H_DIM + h]);
    double Are = -exp((double)log_A_real[t]);
    double Aim = (double)A_imag[t];
    double xre = Are * dt, xim = Aim * dt;

    double ex = exp(xre);
    double sy, cy;
    sincos(xim, &sy, &cy);
    double wre = ex * cy, wim = ex * sy;

    double em1re = ex * cy - 1.0;
    double em1im = ex * sy;

    double den = Are * Are + Aim * Aim;
    double fre = (em1re * Are + em1im * Aim) / den;
    double fim = (em1im * Are - em1re * Aim) / den;
    double cre = (double)C_re[t], cim = (double)C_im[t];
    double c2re = 2.0 * (cre * fre - cim * fim);
    double c2im = 2.0 * (cre * fim + cim * fre);

    double pre = exp(xre * (double)CHLEN);
    double ps, pc;
    sincos(xim * (double)CHLEN, &ps, &pc);

    int S = H_DIM * NC;
    int base = layer * 6 * S + hn;
    g_par[base]         = (float)wre;
    g_par[base + S]     = (float)wim;
    g_par[base + 2 * S] = (float)c2re;
    g_par[base + 3 * S] = (float)c2im;
    g_par[base + 4 * S] = (float)(pre * pc);
    g_par[base + 5 * S] = (float)(pre * ps);
}

// -------- weight repack: g_Wd[layer][o64][k][c*2+{0,1}] = out_W[layer][o64+c*64][k]
__global__ void wt_kernel(const float* __restrict__ out_W) {
    int t = blockIdx.x * blockDim.x + threadIdx.x;
    if (t >= NL * 64 * H_DIM * 4) return;
    int c     = t & 3;
    int k     = (t >> 2) % H_DIM;
    int o64   = (t >> 2) / H_DIM % 64;
    int layer = t / (4 * H_DIM * 64);
    float v = out_W[(layer * 2 * H_DIM + o64 + c * 64) * H_DIM + k];
    int base = (((layer * 64 + o64) * H_DIM) + k) * 8 + c * 2;
    g_Wd[base]     = v;
    g_Wd[base + 1] = v;
}

// ---------------- encoder ----------------
__global__ void enc_kernel(const float* __restrict__ x,
                           const float* __restrict__ enc_W,
                           const float* __restrict__ enc_b) {
    int t = blockIdx.x * blockDim.x + threadIdx.x;
    if (t >= NSEQ * (L_SEQ / 4)) return;
    int l4  = t % (L_SEQ / 4);
    int seq = t / (L_SEQ / 4);
    int b = seq / H_DIM;
    int h = seq % H_DIM;
    float w0 = enc_W[h];
    float w1 = enc_W[H_DIM + h];
    float bb = enc_b[h];
    float4 a = ((const float4*)(x + (b * D_IN + 0) * L_SEQ))[l4];
    float4 c = ((const float4*)(x + (b * D_IN + 1) * L_SEQ))[l4];
    float4 r;
    r.x = fmaf(w1, c.x, fmaf(w0, a.x, bb));
    r.y = fmaf(w1, c.y, fmaf(w0, a.y, bb));
    r.z = fmaf(w1, c.z, fmaf(w0, a.z, bb));
    r.w = fmaf(w1, c.w, fmaf(w0, a.w, bb));
    ((float4*)(g_h + seq * L_SEQ))[l4] = r;
}

// ---------------- pass 1: zero-init chunk-end states, chunks 0..CHUNKS-2 --------
__global__ void pass1_kernel(int layer) {
    int gid  = blockIdx.x * blockDim.x + threadIdx.x;
    int quarter = gid & 3;
    int pair = gid >> 2;
    int chunk = pair % (CHUNKS - 1);
    int seq   = pair / (CHUNKS - 1);
    int h = seq % H_DIM;

    const float* par = g_par + layer * 6 * H_DIM * NC;
    int S  = H_DIM * NC;
    int pb = h * NC + quarter * SPT;

    u64 wre2[NG], wim2[NG], nwim2[NG], sre2[NG], sim2[NG];
#pragma unroll
    for (int g = 0; g < NG; g++) {
        float2 wr = *(const float2*)(par + pb + 2 * g);
        float2 wi = *(const float2*)(par + S + pb + 2 * g);
        wre2[g]  = pk(wr.x, wr.y);
        wim2[g]  = pk(wi.x, wi.y);
        nwim2[g] = pk(-wi.x, -wi.y);
        sre2[g] = 0ull; sim2[g] = 0ull;
    }

    const float4* u4 = (const float4*)(g_h + seq * L_SEQ + chunk * CHLEN);
    for (int l = 0; l < CHLEN / 4; l++) {
        float4 u = u4[l];
        float uu[4] = {u.x, u.y, u.z, u.w};
#pragma unroll
        for (int q = 0; q < 4; q++) {
            u64 u2 = pk(uu[q], uu[q]);
#pragma unroll
            for (int g = 0; g < NG; g++) {
                u64 nr = fma2(nwim2[g], sim2[g], fma2(wre2[g], sre2[g], u2));
                u64 ni = fma2(wre2[g], sim2[g], mul2(wim2[g], sre2[g]));
                sre2[g] = nr; sim2[g] = ni;
            }
        }
    }

    float2* E = g_E + (seq * (CHUNKS - 1) + chunk) * NC + quarter * SPT;
#pragma unroll
    for (int g = 0; g < NG; g++) {
        float r0, r1, i0, i1;
        upk(sre2[g], r0, r1);
        upk(sim2[g], i0, i1);
        E[2 * g]     = make_float2(r0, i0);
        E[2 * g + 1] = make_float2(r1, i1);
    }
}

// ---------------- pass 2: exact recurrence + D skip + gelu -> g_y ----------------
__global__ void pass2_kernel(int layer, const float* __restrict__ Dvec) {
    int gid  = blockIdx.x * blockDim.x + threadIdx.x;
    int quarter = gid & 3;
    int rest = gid >> 2;
    int chunk = rest % CHUNKS;
    int seq   = rest / CHUNKS;
    int h = seq % H_DIM;

    const float* par = g_par + layer * 6 * H_DIM * NC;
    int S  = H_DIM * NC;
    int pb = h * NC + quarter * SPT;

    u64 sre2[NG], sim2[NG];
#pragma unroll
    for (int g = 0; g < NG; g++) { sre2[g] = 0ull; sim2[g] = 0ull; }

    if (chunk > 0) {
        u64 wpre2[NG], wpim2[NG], nwpim2[NG];
#pragma unroll
        for (int g = 0; g < NG; g++) {
            float2 wr = *(const float2*)(par + 4 * S + pb + 2 * g);
            float2 wi = *(const float2*)(par + 5 * S + pb + 2 * g);
            wpre2[g]  = pk(wr.x, wr.y);
            wpim2[g]  = pk(wi.x, wi.y);
            nwpim2[g] = pk(-wi.x, -wi.y);
        }
        for (int c = 0; c < chunk; c++) {
            const float2* E = g_E + (seq * (CHUNKS - 1) + c) * NC + quarter * SPT;
#pragma unroll
            for (int g = 0; g < NG; g++) {
                float2 e0 = E[2 * g], e1 = E[2 * g + 1];
                u64 re2 = pk(e0.x, e1.x);
                u64 im2 = pk(e0.y, e1.y);
                u64 nr = fma2(wpre2[g], sre2[g], fma2(nwpim2[g], sim2[g], re2));
                u64 ni = fma2(wpre2[g], sim2[g], fma2(wpim2[g], sre2[g], im2));
                sre2[g] = nr; sim2[g] = ni;
            }
        }
    }

    u64 wre2[NG], wim2[NG], nwim2[NG], cr2[NG], nci2[NG];
#pragma unroll
    for (int g = 0; g < NG; g++) {
        float2 wr = *(const float2*)(par + pb + 2 * g);
        float2 wi = *(const float2*)(par + S + pb + 2 * g);
        float2 cr = *(const float2*)(par + 2 * S + pb + 2 * g);
        float2 ci = *(const float2*)(par + 3 * S + pb + 2 * g);
        wre2[g]  = pk(wr.x, wr.y);
        wim2[g]  = pk(wi.x, wi.y);
        nwim2[g] = pk(-wi.x, -wi.y);
        cr2[g]   = pk(cr.x, cr.y);
        nci2[g]  = pk(-ci.x, -ci.y);
    }
    float Dh = Dvec[layer * H_DIM + h];

    const float4* u4 = (const float4*)(g_h + seq * L_SEQ + chunk * CHLEN);
    float4*       y4 = (float4*)(g_y + seq * L_SEQ + chunk * CHLEN);

    for (int l = 0; l < CHLEN / 4; l++) {
        float4 u = u4[l];
        float uu[4] = {u.x, u.y, u.z, u.w};
        float out[4];
#pragma unroll
        for (int q = 0; q < 4; q++) {
            float uv = uu[q];
            u64 u2 = pk(uv, uv);
            u64 acc2 = 0ull;
#pragma unroll
            for (int g = 0; g < NG; g++) {
                u64 nr = fma2(nwim2[g], sim2[g], fma2(wre2[g], sre2[g], u2));
                u64 ni = fma2(wre2[g], sim2[g], mul2(wim2[g], sre2[g]));
                sre2[g] = nr; sim2[g] = ni;
                acc2 = fma2(cr2[g], nr, acc2);
                acc2 = fma2(nci2[g], ni, acc2);
            }
            float alo, ahi;
            upk(acc2, alo, ahi);
            float acc = alo + ahi;
            acc += __shfl_xor_sync(0xffffffffu, acc, 1);
            acc += __shfl_xor_sync(0xffffffffu, acc, 2);
            float yv = fmaf(uv, Dh, acc);
            out[q] = 0.5f * yv * (1.f + erff(yv * 0.7071067811865476f));
        }
        if (quarter == 0) y4[l] = make_float4(out[0], out[1], out[2], out[3]);
    }
}

// -------- GLU GEMM + residual + LayerNorm; 4 outputs/thread, smem-staged y -------
__global__ void glu_kernel(int layer,
                           const float* __restrict__ out_b,
                           const float* __restrict__ ln_g,
                           const float* __restrict__ ln_b) {
    __shared__ float  ys[H_DIM][LT2];    // y tile: [k][l] 16KB
    __shared__ float  zt[LT2][H_DIM];    // post-GLU+residual 16KB
    __shared__ float2 mv[LT2];

    int bl = blockIdx.x;
    int b  = bl / (L_SEQ / LT2);
    int l0 = (bl % (L_SEQ / LT2)) * LT2;
    int t  = threadIdx.x;                // 128
    int lh = t >> 6;                     // 0/1 -> which 16-l half
    int o  = t & 63;
    int lbase = l0 + lh * 16;

    // stage y tile: thread t loads row k=t (32 floats contiguous)
    {
        const float4* src = (const float4*)(g_y + (b * H_DIM + t) * L_SEQ + l0);
        float4* dst = (float4*)&ys[t][0];
#pragma unroll
        for (int i = 0; i < LT2 / 4; i++) dst[i] = __ldg(src + i);
    }
    __syncthreads();

    // accumulators: A[o], A[o+64], G[o], G[o+64] x 16 l (8 f32x2 each)
    float bA0 = out_b[layer * 2 * H_DIM + o];
    float bA1 = out_b[layer * 2 * H_DIM + o + 64];
    float bG0 = out_b[layer * 2 * H_DIM + 128 + o];
    float bG1 = out_b[layer * 2 * H_DIM + 192 + o];
    u64 aA0[8], aA1[8], aG0[8], aG1[8];
#pragma unroll
    for (int g = 0; g < 8; g++) {
        aA0[g] = pk(bA0, bA0); aA1[g] = pk(bA1, bA1);
        aG0[g] = pk(bG0, bG0); aG1[g] = pk(bG1, bG1);
    }

    const ulonglong2* wp =
        (const ulonglong2*)(g_Wd + (((layer * 64 + o) * H_DIM)) * 8);
#pragma unroll 4
    for (int k = 0; k < H_DIM; k++) {
        ulonglong2 w01 = __ldg(wp);        // (A[o] dup, A[o+64] dup)
        ulonglong2 w23 = __ldg(wp + 1);    // (G[o] dup, G[o+64] dup)
        wp += 2;
        const ulonglong2* yr = (const ulonglong2*)&ys[k][lh * 16];
        ulonglong2 q0 = yr[0], q1 = yr[1], q2 = yr[2], q3 = yr[3];
        u64 yp[8] = {q0.x, q0.y, q1.x, q1.y, q2.x, q2.y, q3.x, q3.y};
#pragma unroll
        for (int g = 0; g < 8; g++) {
            aA0[g] = fma2(w01.x, yp[g], aA0[g]);
            aA1[g] = fma2(w01.y, yp[g], aA1[g]);
            aG0[g] = fma2(w23.x, yp[g], aG0[g]);
            aG1[g] = fma2(w23.y, yp[g], aG1[g]);
        }
    }

    // residual rows for o and o+64 at this thread's 16 l's
    float hv0[16], hv1[16];
    {
        const float4* h0p = (const float4*)(g_h + (b * H_DIM + o) * L_SEQ + lbase);
        const float4* h1p = (const float4*)(g_h + (b * H_DIM + o + 64) * L_SEQ + lbase);
#pragma unroll
        for (int i = 0; i < 4; i++) {
            ((float4*)hv0)[i] = h0p[i];
            ((float4*)hv1)[i] = h1p[i];
        }
    }

#pragma unroll
    for (int g = 0; g < 8; g++) {
        float x0, x1, gg0, gg1;
        upk(aA0[g], x0, x1);
        upk(aG0[g], gg0, gg1);
        float s0 = 1.f / (1.f + expf(-gg0));
        float s1 = 1.f / (1.f + expf(-gg1));
        zt[lh * 16 + 2 * g][o]     = fmaf(x0, s0, hv0[2 * g]);
        zt[lh * 16 + 2 * g + 1][o] = fmaf(x1, s1, hv0[2 * g + 1]);
        upk(aA1[g], x0, x1);
        upk(aG1[g], gg0, gg1);
        s0 = 1.f / (1.f + expf(-gg0));
        s1 = 1.f / (1.f + expf(-gg1));
        zt[lh * 16 + 2 * g][o + 64]     = fmaf(x0, s0, hv1[2 * g]);
        zt[lh * 16 + 2 * g + 1][o + 64] = fmaf(x1, s1, hv1[2 * g + 1]);
    }
    __syncthreads();

    int w = t >> 5, lane = t & 31;
#pragma unroll
    for (int l = w; l < LT2; l += 4) {
        float v0 = zt[l][lane], v1 = zt[l][lane + 32];
        float v2 = zt[l][lane + 64], v3 = zt[l][lane + 96];
        float s = v0 + v1 + v2 + v3;
        float q = fmaf(v0, v0, fmaf(v1, v1, fmaf(v2, v2, v3 * v3)));
#pragma unroll
        for (int off = 16; off > 0; off >>= 1) {
            s += __shfl_xor_sync(0xffffffffu, s, off);
            q += __shfl_xor_sync(0xffffffffu, q, off);
        }
        if (lane == 0) {
            float m   = s * (1.0f / H_DIM);
            float var = q * (1.0f / H_DIM) - m * m;
            mv[l] = make_float2(m, rsqrtf(var + 1e-5f));
        }
    }
    __syncthreads();

    // normalize + write back this thread's two rows (o, o+64), 16 l's each
    {
        float gam0 = ln_g[layer * H_DIM + o];
        float bet0 = ln_b[layer * H_DIM + o];
        float gam1 = ln_g[layer * H_DIM + o + 64];
        float bet1 = ln_b[layer * H_DIM + o + 64];
        float r0[16], r1[16];
#pragma unroll
        for (int l = 0; l < 16; l++) {
            int lr = lh * 16 + l;
            float2 m = mv[lr];
            r0[l] = fmaf((zt[lr][o] - m.x) * m.y, gam0, bet0);
            r1[l] = fmaf((zt[lr][o + 64] - m.x) * m.y, gam1, bet1);
        }
        float4* w0p = (float4*)(g_h + (b * H_DIM + o) * L_SEQ + lbase);
        float4* w1p = (float4*)(g_h + (b * H_DIM + o + 64) * L_SEQ + lbase);
#pragma unroll
        for (int i = 0; i < 4; i++) {
            w0p[i] = ((float4*)r0)[i];
            w1p[i] = ((float4*)r1)[i];
        }
    }
}

// ---------------- mean over L ----------------
__global__ void pool_kernel() {
    int seq = blockIdx.x;
    int t   = threadIdx.x;    // 256 threads
    const float4* r = (const float4*)(g_h + seq * L_SEQ);
    float s = 0.f;
    for (int i = t; i < L_SEQ / 4; i += 256) {
        float4 v = r[i];
        s += v.x + v.y + v.z + v.w;
    }
    __shared__ float sm[256];
    sm[t] = s;
    __syncthreads();
    for (int off = 128; off > 0; off >>= 1) {
        if (t < off) sm[t] += sm[t + off];
        __syncthreads();
    }
    if (t == 0) g_pooled[seq] = sm[0] * (1.f / L_SEQ);
}

// ---------------- head ----------------
__global__ void head_kernel(const float* __restrict__ head_W,
                            const float* __restrict__ head_b,
                            float* __restrict__ out) {
    int t = threadIdx.x;
    if (t >= B_SZ * D_OUT) return;
    int b = t / D_OUT, o = t % D_OUT;
    float s = head_b[o];
    for (int h = 0; h < H_DIM; h++)
        s = fmaf(g_pooled[b * H_DIM + h], head_W[h * D_OUT + o], s);
    out[t] = s;
}

// ---------------- launch ----------------
extern "C" void kernel_launch(void* const* d_in, const int* in_sizes, int n_in,
                              void* d_out, int out_size) {
    const float* x          = (const float*)d_in[0];
    const float* enc_W      = (const float*)d_in[1];
    const float* enc_b      = (const float*)d_in[2];
    const float* log_dt     = (const float*)d_in[3];
    const float* C_re       = (const float*)d_in[4];
    const float* C_im       = (const float*)d_in[5];
    const float* log_A_real = (const float*)d_in[6];
    const float* A_imag     = (const float*)d_in[7];
    const float* Dvec       = (const float*)d_in[8];
    const float* out_W      = (const float*)d_in[9];
    const float* out_b      = (const float*)d_in[10];
    const float* ln_g       = (const float*)d_in[11];
    const float* ln_b       = (const float*)d_in[12];
    const float* head_W     = (const float*)d_in[13];
    const float* head_b     = (const float*)d_in[14];
    float* out = (float*)d_out;

    param_kernel<<<(NL * H_DIM * NC + 127) / 128, 128>>>(log_dt, C_re, C_im,
                                                         log_A_real, A_imag);
    wt_kernel<<<(NL * 64 * H_DIM * 4 + 255) / 256, 256>>>(out_W);
    enc_kernel<<<(NSEQ * (L_SEQ / 4)) / 256, 256>>>(x, enc_W, enc_b);

    for (int layer = 0; layer < NL; layer++) {
        pass1_kernel<<<(NSEQ * (CHUNKS - 1) * 4) / 128, 128>>>(layer);
        pass2_kernel<<<(NSEQ * CHUNKS * 4) / 128, 128>>>(layer, Dvec);
        glu_kernel<<<B_SZ * (L_SEQ / LT2), 128>>>(layer, out_b, ln_g, ln_b);
    }

    pool_kernel<<<NSEQ, 256>>>();
    head_kernel<<<1, 64>>>(head_W, head_b, out);
}

// round 4
// speedup vs baseline: 1.5052x; 1.5052x over previous
#include <cuda_runtime.h>
#include <math.h>

#define B_SZ   32
#define D_IN   2
#define L_SEQ  4096
#define H_DIM  128
#define NL     6
#define NC     32
#define D_OUT  2
#define NSEQ   (B_SZ * H_DIM)        // 4096
#define CHUNKS 8
#define CHLEN  (L_SEQ / CHUNKS)      // 512
#define SPT    8                     // states per thread (4 threads per seq-chunk)
#define NG     (SPT / 2)             // packed f32x2 groups per thread = 4
#define GLT    16                    // l-tile for GLU kernel

typedef unsigned long long u64;

// ---------------- f32x2 helpers (sm_103a packed FMA) ----------------
__device__ __forceinline__ u64 pk(float lo, float hi) {
    u64 r;
    asm("mov.b64 %0, {%1, %2};" : "=l"(r) : "r"(__float_as_uint(lo)), "r"(__float_as_uint(hi)));
    return r;
}
__device__ __forceinline__ void upk(u64 a, float& lo, float& hi) {
    unsigned int x, y;
    asm("mov.b64 {%0, %1}, %2;" : "=r"(x), "=r"(y) : "l"(a));
    lo = __uint_as_float(x); hi = __uint_as_float(y);
}
__device__ __forceinline__ u64 fma2(u64 a, u64 b, u64 c) {
    u64 d;
    asm("fma.rn.f32x2 %0, %1, %2, %3;" : "=l"(d) : "l"(a), "l"(b), "l"(c));
    return d;
}
__device__ __forceinline__ u64 mul2(u64 a, u64 b) {
    u64 d;
    asm("mul.rn.f32x2 %0, %1, %2;" : "=l"(d) : "l"(a), "l"(b));
    return d;
}

// ---------------- scratch (static device arrays; no allocation) ----------------
__device__ float  g_h[NSEQ * L_SEQ];                 // current activations (B,H,L)
__device__ float  g_y[NSEQ * L_SEQ];                 // SSM output post-gelu (B,H,L)
__device__ float2 g_E[NSEQ * (CHUNKS - 1) * NC];     // chunk-end states
__device__ float  g_par[NL * 6 * H_DIM * NC];        // wre,wim,c2re,c2im,wpre,wpim
__device__ float  g_Wt[NL * H_DIM * 2 * H_DIM];      // transposed out_W: [layer][k][o]
__device__ float  g_pooled[NSEQ];

// ---------------- per-layer parameter precompute (double for accuracy) ----------
__global__ void param_kernel(const float* __restrict__ log_dt,
                             const float* __restrict__ C_re,
                             const float* __restrict__ C_im,
                             const float* __restrict__ log_A_real,
                             const float* __restrict__ A_imag) {
    int t = blockIdx.x * blockDim.x + threadIdx.x;
    if (t >= NL * H_DIM * NC) return;
    int layer = t / (H_DIM * NC);
    int hn    = t % (H_DIM * NC);
    int h     = hn / NC;

    double dt  = exp((double)log_dt[layer * H_DIM + h]);
    double Are = -exp((double)log_A_real[t]);
    double Aim = (double)A_imag[t];
    double xre = Are * dt, xim = Aim * dt;

    double ex = exp(xre);
    double sy, cy;
    sincos(xim, &sy, &cy);
    double wre = ex * cy, wim = ex * sy;

    double em1re = ex * cy - 1.0;
    double em1im = ex * sy;

    double den = Are * Are + Aim * Aim;
    double fre = (em1re * Are + em1im * Aim) / den;
    double fim = (em1im * Are - em1re * Aim) / den;
    double cre = (double)C_re[t], cim = (double)C_im[t];
    double c2re = 2.0 * (cre * fre - cim * fim);
    double c2im = 2.0 * (cre * fim + cim * fre);

    double pre = exp(xre * (double)CHLEN);
    double ps, pc;
    sincos(xim * (double)CHLEN, &ps, &pc);

    int S = H_DIM * NC;
    int base = layer * 6 * S + hn;
    g_par[base]         = (float)wre;
    g_par[base + S]     = (float)wim;
    g_par[base + 2 * S] = (float)c2re;
    g_par[base + 3 * S] = (float)c2im;
    g_par[base + 4 * S] = (float)(pre * pc);
    g_par[base + 5 * S] = (float)(pre * ps);
}

// ---------------- transpose out_W -> [layer][k][o] ----------------
__global__ void wt_kernel(const float* __restrict__ out_W) {
    int t = blockIdx.x * blockDim.x + threadIdx.x;
    if (t >= NL * 2 * H_DIM * H_DIM) return;
    int layer = t / (2 * H_DIM * H_DIM);
    int r     = t % (2 * H_DIM * H_DIM);
    int o = r / H_DIM;
    int k = r % H_DIM;
    g_Wt[layer * 2 * H_DIM * H_DIM + k * 2 * H_DIM + o] = out_W[t];
}

// ---------------- encoder ----------------
__global__ void enc_kernel(const float* __restrict__ x,
                           const float* __restrict__ enc_W,
                           const float* __restrict__ enc_b) {
    int t = blockIdx.x * blockDim.x + threadIdx.x;
    if (t >= NSEQ * (L_SEQ / 4)) return;
    int l4  = t % (L_SEQ / 4);
    int seq = t / (L_SEQ / 4);
    int b = seq / H_DIM;
    int h = seq % H_DIM;
    float w0 = enc_W[h];
    float w1 = enc_W[H_DIM + h];
    float bb = enc_b[h];
    float4 a = ((const float4*)(x + (b * D_IN + 0) * L_SEQ))[l4];
    float4 c = ((const float4*)(x + (b * D_IN + 1) * L_SEQ))[l4];
    float4 r;
    r.x = fmaf(w1, c.x, fmaf(w0, a.x, bb));
    r.y = fmaf(w1, c.y, fmaf(w0, a.y, bb));
    r.z = fmaf(w1, c.z, fmaf(w0, a.z, bb));
    r.w = fmaf(w1, c.w, fmaf(w0, a.w, bb));
    ((float4*)(g_h + seq * L_SEQ))[l4] = r;
}

// ---------------- pass 1: zero-init chunk-end states, chunks 0..CHUNKS-2 --------
__global__ void pass1_kernel(int layer) {
    int gid  = blockIdx.x * blockDim.x + threadIdx.x;
    int quarter = gid & 3;
    int pair = gid >> 2;
    int chunk = pair % (CHUNKS - 1);
    int seq   = pair / (CHUNKS - 1);
    int h = seq % H_DIM;

    const float* par = g_par + layer * 6 * H_DIM * NC;
    int S  = H_DIM * NC;
    int pb = h * NC + quarter * SPT;

    u64 wre2[NG], wim2[NG], nwim2[NG], sre2[NG], sim2[NG];
#pragma unroll
    for (int g = 0; g < NG; g++) {
        float2 wr = *(const float2*)(par + pb + 2 * g);
        float2 wi = *(const float2*)(par + S + pb + 2 * g);
        wre2[g]  = pk(wr.x, wr.y);
        wim2[g]  = pk(wi.x, wi.y);
        nwim2[g] = pk(-wi.x, -wi.y);
        sre2[g] = 0ull; sim2[g] = 0ull;
    }

    const float4* u4 = (const float4*)(g_h + seq * L_SEQ + chunk * CHLEN);
    for (int l = 0; l < CHLEN / 4; l++) {
        float4 u = u4[l];
        float uu[4] = {u.x, u.y, u.z, u.w};
#pragma unroll
        for (int q = 0; q < 4; q++) {
            u64 u2 = pk(uu[q], uu[q]);
#pragma unroll
            for (int g = 0; g < NG; g++) {
                u64 nr = fma2(nwim2[g], sim2[g], fma2(wre2[g], sre2[g], u2));
                u64 ni = fma2(wre2[g], sim2[g], mul2(wim2[g], sre2[g]));
                sre2[g] = nr; sim2[g] = ni;
            }
        }
    }

    float2* E = g_E + (seq * (CHUNKS - 1) + chunk) * NC + quarter * SPT;
#pragma unroll
    for (int g = 0; g < NG; g++) {
        float r0, r1, i0, i1;
        upk(sre2[g], r0, r1);
        upk(sim2[g], i0, i1);
        E[2 * g]     = make_float2(r0, i0);
        E[2 * g + 1] = make_float2(r1, i1);
    }
}

// ---------------- pass 2: exact recurrence + D skip + gelu -> g_y ----------------
__global__ void pass2_kernel(int layer, const float* __restrict__ Dvec) {
    int gid  = blockIdx.x * blockDim.x + threadIdx.x;
    int quarter = gid & 3;
    int rest = gid >> 2;
    int chunk = rest % CHUNKS;
    int seq   = rest / CHUNKS;
    int h = seq % H_DIM;

    const float* par = g_par + layer * 6 * H_DIM * NC;
    int S  = H_DIM * NC;
    int pb = h * NC + quarter * SPT;

    u64 sre2[NG], sim2[NG];
#pragma unroll
    for (int g = 0; g < NG; g++) { sre2[g] = 0ull; sim2[g] = 0ull; }

    if (chunk > 0) {
        u64 wpre2[NG], wpim2[NG], nwpim2[NG];
#pragma unroll
        for (int g = 0; g < NG; g++) {
            float2 wr = *(const float2*)(par + 4 * S + pb + 2 * g);
            float2 wi = *(const float2*)(par + 5 * S + pb + 2 * g);
            wpre2[g]  = pk(wr.x, wr.y);
            wpim2[g]  = pk(wi.x, wi.y);
            nwpim2[g] = pk(-wi.x, -wi.y);
        }
        for (int c = 0; c < chunk; c++) {
            const float2* E = g_E + (seq * (CHUNKS - 1) + c) * NC + quarter * SPT;
#pragma unroll
            for (int g = 0; g < NG; g++) {
                float2 e0 = E[2 * g], e1 = E[2 * g + 1];
                u64 re2 = pk(e0.x, e1.x);
                u64 im2 = pk(e0.y, e1.y);
                u64 nr = fma2(wpre2[g], sre2[g], fma2(nwpim2[g], sim2[g], re2));
                u64 ni = fma2(wpre2[g], sim2[g], fma2(wpim2[g], sre2[g], im2));
                sre2[g] = nr; sim2[g] = ni;
            }
        }
    }

    u64 wre2[NG], wim2[NG], nwim2[NG], cr2[NG], nci2[NG];
#pragma unroll
    for (int g = 0; g < NG; g++) {
        float2 wr = *(const float2*)(par + pb + 2 * g);
        float2 wi = *(const float2*)(par + S + pb + 2 * g);
        float2 cr = *(const float2*)(par + 2 * S + pb + 2 * g);
        float2 ci = *(const float2*)(par + 3 * S + pb + 2 * g);
        wre2[g]  = pk(wr.x, wr.y);
        wim2[g]  = pk(wi.x, wi.y);
        nwim2[g] = pk(-wi.x, -wi.y);
        cr2[g]   = pk(cr.x, cr.y);
        nci2[g]  = pk(-ci.x, -ci.y);
    }
    float Dh = Dvec[layer * H_DIM + h];

    const float4* u4 = (const float4*)(g_h + seq * L_SEQ + chunk * CHLEN);
    float4*       y4 = (float4*)(g_y + seq * L_SEQ + chunk * CHLEN);

    for (int l = 0; l < CHLEN / 4; l++) {
        float4 u = u4[l];
        float uu[4] = {u.x, u.y, u.z, u.w};
        float out[4];
#pragma unroll
        for (int q = 0; q < 4; q++) {
            float uv = uu[q];
            u64 u2 = pk(uv, uv);
            u64 acc2 = 0ull;
#pragma unroll
            for (int g = 0; g < NG; g++) {
                u64 nr = fma2(nwim2[g], sim2[g], fma2(wre2[g], sre2[g], u2));
                u64 ni = fma2(wre2[g], sim2[g], mul2(wim2[g], sre2[g]));
                sre2[g] = nr; sim2[g] = ni;
                acc2 = fma2(cr2[g], nr, acc2);
                acc2 = fma2(nci2[g], ni, acc2);
            }
            float alo, ahi;
            upk(acc2, alo, ahi);
            float acc = alo + ahi;
            acc += __shfl_xor_sync(0xffffffffu, acc, 1);
            acc += __shfl_xor_sync(0xffffffffu, acc, 2);
            float yv = fmaf(uv, Dh, acc);
            out[q] = 0.5f * yv * (1.f + erff(yv * 0.7071067811865476f));
        }
        if (quarter == 0) y4[l] = make_float4(out[0], out[1], out[2], out[3]);
    }
}

// -------- GLU GEMM + residual + LayerNorm; 1 output row/thread, smem-staged y ----
// 256 threads: thread o owns output channel o (A for o<128, G for o>=128) over
// a 16-l tile -> only 8 u64 accumulators. Per k: 1 LDG(w) + 1 pk + 4 LDS.128 +
// 8 fma2.
__global__ void __launch_bounds__(256) glu_kernel(int layer,
                           const float* __restrict__ out_b,
                           const float* __restrict__ ln_g,
                           const float* __restrict__ ln_b) {
    __shared__ float  ys[H_DIM][GLT];       // y tile [k][l]  8KB
    __shared__ float  ag[2][GLT][H_DIM];    // A/G transpose  16KB (reused for z)
    __shared__ float2 mv[GLT];

    int bl = blockIdx.x;
    int b  = bl / (L_SEQ / GLT);
    int l0 = (bl % (L_SEQ / GLT)) * GLT;
    int t  = threadIdx.x;                   // 256

    // stage y tile: 2 threads per row k, 8 floats each
    {
        int k = t >> 1, hf = t & 1;
        const float4* src = (const float4*)(g_y + (b * H_DIM + k) * L_SEQ + l0 + hf * 8);
        float4* dst = (float4*)&ys[k][hf * 8];
        dst[0] = __ldg(src);
        dst[1] = __ldg(src + 1);
    }
    __syncthreads();

    // GEMM: acc[g] covers l = 2g, 2g+1
    float bias = out_b[layer * 2 * H_DIM + t];
    u64 acc[8];
#pragma unroll
    for (int g = 0; g < 8; g++) acc[g] = pk(bias, bias);

    const float* wrow = g_Wt + layer * 2 * H_DIM * H_DIM + t;
#pragma unroll 4
    for (int k = 0; k < H_DIM; k++) {
        float w = __ldg(wrow + k * 2 * H_DIM);
        u64 w2 = pk(w, w);
        const ulonglong2* yr = (const ulonglong2*)&ys[k][0];
        ulonglong2 q0 = yr[0], q1 = yr[1], q2 = yr[2], q3 = yr[3];
        acc[0] = fma2(w2, q0.x, acc[0]);
        acc[1] = fma2(w2, q0.y, acc[1]);
        acc[2] = fma2(w2, q1.x, acc[2]);
        acc[3] = fma2(w2, q1.y, acc[3]);
        acc[4] = fma2(w2, q2.x, acc[4]);
        acc[5] = fma2(w2, q2.y, acc[5]);
        acc[6] = fma2(w2, q3.x, acc[6]);
        acc[7] = fma2(w2, q3.y, acc[7]);
    }

    // scatter to ag[is_gate][l][channel]
    {
        int ch = t & 127, sel = t >> 7;
#pragma unroll
        for (int g = 0; g < 8; g++) {
            float v0, v1;
            upk(acc[g], v0, v1);
            ag[sel][2 * g][ch]     = v0;
            ag[sel][2 * g + 1][ch] = v1;
        }
    }
    __syncthreads();

    // GLU + residual: thread handles (ch = t&127, 8 l's selected by t>>7)
    {
        int ch = t & 127, lh = t >> 7;
        const float4* hp = (const float4*)(g_h + (b * H_DIM + ch) * L_SEQ + l0 + lh * 8);
        float hv[8];
        ((float4*)hv)[0] = hp[0];
        ((float4*)hv)[1] = hp[1];
#pragma unroll
        for (int i = 0; i < 8; i++) {
            int l = lh * 8 + i;
            float a = ag[0][l][ch];
            float gte = ag[1][l][ch];
            float s = 1.f / (1.f + expf(-gte));
            ag[0][l][ch] = fmaf(a, s, hv[i]);   // z = GLU + residual (in place)
        }
    }
    __syncthreads();

    // LayerNorm stats per l (8 warps cover 16 l in 2 rounds)
    {
        int w = t >> 5, lane = t & 31;
#pragma unroll
        for (int l = w; l < GLT; l += 8) {
            float v0 = ag[0][l][lane],      v1 = ag[0][l][lane + 32];
            float v2 = ag[0][l][lane + 64], v3 = ag[0][l][lane + 96];
            float s = v0 + v1 + v2 + v3;
            float q = fmaf(v0, v0, fmaf(v1, v1, fmaf(v2, v2, v3 * v3)));
#pragma unroll
            for (int off = 16; off > 0; off >>= 1) {
                s += __shfl_xor_sync(0xffffffffu, s, off);
                q += __shfl_xor_sync(0xffffffffu, q, off);
            }
            if (lane == 0) {
                float m   = s * (1.0f / H_DIM);
                float var = q * (1.0f / H_DIM) - m * m;
                mv[l] = make_float2(m, rsqrtf(var + 1e-5f));
            }
        }
    }
    __syncthreads();

    // normalize + write back
    {
        int ch = t & 127, lh = t >> 7;
        float gam = ln_g[layer * H_DIM + ch];
        float bet = ln_b[layer * H_DIM + ch];
        float r[8];
#pragma unroll
        for (int i = 0; i < 8; i++) {
            int l = lh * 8 + i;
            float2 m = mv[l];
            r[i] = fmaf((ag[0][l][ch] - m.x) * m.y, gam, bet);
        }
        float4* wp = (float4*)(g_h + (b * H_DIM + ch) * L_SEQ + l0 + lh * 8);
        wp[0] = ((float4*)r)[0];
        wp[1] = ((float4*)r)[1];
    }
}

// ---------------- mean over L ----------------
__global__ void pool_kernel() {
    int seq = blockIdx.x;
    int t   = threadIdx.x;    // 256 threads
    const float4* r = (const float4*)(g_h + seq * L_SEQ);
    float s = 0.f;
    for (int i = t; i < L_SEQ / 4; i += 256) {
        float4 v = r[i];
        s += v.x + v.y + v.z + v.w;
    }
    __shared__ float sm[256];
    sm[t] = s;
    __syncthreads();
    for (int off = 128; off > 0; off >>= 1) {
        if (t < off) sm[t] += sm[t + off];
        __syncthreads();
    }
    if (t == 0) g_pooled[seq] = sm[0] * (1.f / L_SEQ);
}

// ---------------- head ----------------
__global__ void head_kernel(const float* __restrict__ head_W,
                            const float* __restrict__ head_b,
                            float* __restrict__ out) {
    int t = threadIdx.x;
    if (t >= B_SZ * D_OUT) return;
    int b = t / D_OUT, o = t % D_OUT;
    float s = head_b[o];
    for (int h = 0; h < H_DIM; h++)
        s = fmaf(g_pooled[b * H_DIM + h], head_W[h * D_OUT + o], s);
    out[t] = s;
}

// ---------------- launch ----------------
extern "C" void kernel_launch(void* const* d_in, const int* in_sizes, int n_in,
                              void* d_out, int out_size) {
    const float* x          = (const float*)d_in[0];
    const float* enc_W      = (const float*)d_in[1];
    const float* enc_b      = (const float*)d_in[2];
    const float* log_dt     = (const float*)d_in[3];
    const float* C_re       = (const float*)d_in[4];
    const float* C_im       = (const float*)d_in[5];
    const float* log_A_real = (const float*)d_in[6];
    const float* A_imag     = (const float*)d_in[7];
    const float* Dvec       = (const float*)d_in[8];
    const float* out_W      = (const float*)d_in[9];
    const float* out_b      = (const float*)d_in[10];
    const float* ln_g       = (const float*)d_in[11];
    const float* ln_b       = (const float*)d_in[12];
    const float* head_W     = (const float*)d_in[13];
    const float* head_b     = (const float*)d_in[14];
    float* out = (float*)d_out;

    param_kernel<<<(NL * H_DIM * NC + 127) / 128, 128>>>(log_dt, C_re, C_im,
                                                         log_A_real, A_imag);
    wt_kernel<<<(NL * 2 * H_DIM * H_DIM + 255) / 256, 256>>>(out_W);
    enc_kernel<<<(NSEQ * (L_SEQ / 4)) / 256, 256>>>(x, enc_W, enc_b);

    for (int layer = 0; layer < NL; layer++) {
        pass1_kernel<<<(NSEQ * (CHUNKS - 1) * 4) / 128, 128>>>(layer);
        pass2_kernel<<<(NSEQ * CHUNKS * 4) / 128, 128>>>(layer, Dvec);
        glu_kernel<<<B_SZ * (L_SEQ / GLT), 256>>>(layer, out_b, ln_g, ln_b);
    }

    pool_kernel<<<NSEQ, 256>>>();
    head_kernel<<<1, 64>>>(head_W, head_b, out);
}

// round 5
// speedup vs baseline: 1.6030x; 1.0650x over previous
#include <cuda_runtime.h>
#include <math.h>

#define B_SZ   32
#define D_IN   2
#define L_SEQ  4096
#define H_DIM  128
#define NL     6
#define NC     32
#define D_OUT  2
#define NSEQ   (B_SZ * H_DIM)        // 4096
#define CHUNKS 8
#define CHLEN  (L_SEQ / CHUNKS)      // 512
#define SPT    8                     // states per thread (4 threads per seq-chunk)
#define NG     (SPT / 2)             // packed f32x2 groups per thread = 4
#define GLT    32                    // l-tile for GLU kernel

typedef unsigned long long u64;

// ---------------- f32x2 helpers (sm_103a packed FMA) ----------------
__device__ __forceinline__ u64 pk(float lo, float hi) {
    u64 r;
    asm("mov.b64 %0, {%1, %2};" : "=l"(r) : "r"(__float_as_uint(lo)), "r"(__float_as_uint(hi)));
    return r;
}
__device__ __forceinline__ void upk(u64 a, float& lo, float& hi) {
    unsigned int x, y;
    asm("mov.b64 {%0, %1}, %2;" : "=r"(x), "=r"(y) : "l"(a));
    lo = __uint_as_float(x); hi = __uint_as_float(y);
}
__device__ __forceinline__ u64 fma2(u64 a, u64 b, u64 c) {
    u64 d;
    asm("fma.rn.f32x2 %0, %1, %2, %3;" : "=l"(d) : "l"(a), "l"(b), "l"(c));
    return d;
}
__device__ __forceinline__ u64 mul2(u64 a, u64 b) {
    u64 d;
    asm("mul.rn.f32x2 %0, %1, %2;" : "=l"(d) : "l"(a), "l"(b));
    return d;
}

// ---------------- scratch (static device arrays; no allocation) ----------------
__device__ float  g_h[NSEQ * L_SEQ];                 // current activations (B,H,L)
__device__ float  g_y[NSEQ * L_SEQ];                 // SSM output post-gelu (B,H,L)
__device__ float2 g_E[NSEQ * (CHUNKS - 1) * NC];     // chunk-end states
__device__ float  g_par[NL * 6 * H_DIM * NC];        // wre,wim,c2re,c2im,wpre,wpim
__device__ float  g_Wt[NL * H_DIM * 2 * H_DIM];      // transposed out_W: [layer][k][o]
__device__ float  g_pooled[NSEQ];

// ---------------- per-layer parameter precompute (double for accuracy) ----------
__global__ void param_kernel(const float* __restrict__ log_dt,
                             const float* __restrict__ C_re,
                             const float* __restrict__ C_im,
                             const float* __restrict__ log_A_real,
                             const float* __restrict__ A_imag) {
    int t = blockIdx.x * blockDim.x + threadIdx.x;
    if (t >= NL * H_DIM * NC) return;
    int layer = t / (H_DIM * NC);
    int hn    = t % (H_DIM * NC);
    int h     = hn / NC;

    double dt  = exp((double)log_dt[layer * H_DIM + h]);
    double Are = -exp((double)log_A_real[t]);
    double Aim = (double)A_imag[t];
    double xre = Are * dt, xim = Aim * dt;

    double ex = exp(xre);
    double sy, cy;
    sincos(xim, &sy, &cy);
    double wre = ex * cy, wim = ex * sy;

    double em1re = ex * cy - 1.0;
    double em1im = ex * sy;

    double den = Are * Are + Aim * Aim;
    double fre = (em1re * Are + em1im * Aim) / den;
    double fim = (em1im * Are - em1re * Aim) / den;
    double cre = (double)C_re[t], cim = (double)C_im[t];
    double c2re = 2.0 * (cre * fre - cim * fim);
    double c2im = 2.0 * (cre * fim + cim * fre);

    double pre = exp(xre * (double)CHLEN);
    double ps, pc;
    sincos(xim * (double)CHLEN, &ps, &pc);

    int S = H_DIM * NC;
    int base = layer * 6 * S + hn;
    g_par[base]         = (float)wre;
    g_par[base + S]     = (float)wim;
    g_par[base + 2 * S] = (float)c2re;
    g_par[base + 3 * S] = (float)c2im;
    g_par[base + 4 * S] = (float)(pre * pc);
    g_par[base + 5 * S] = (float)(pre * ps);
}

// ---------------- transpose out_W -> [layer][k][o] ----------------
__global__ void wt_kernel(const float* __restrict__ out_W) {
    int t = blockIdx.x * blockDim.x + threadIdx.x;
    if (t >= NL * 2 * H_DIM * H_DIM) return;
    int layer = t / (2 * H_DIM * H_DIM);
    int r     = t % (2 * H_DIM * H_DIM);
    int o = r / H_DIM;
    int k = r % H_DIM;
    g_Wt[layer * 2 * H_DIM * H_DIM + k * 2 * H_DIM + o] = out_W[t];
}

// ---------------- encoder ----------------
__global__ void enc_kernel(const float* __restrict__ x,
                           const float* __restrict__ enc_W,
                           const float* __restrict__ enc_b) {
    int t = blockIdx.x * blockDim.x + threadIdx.x;
    if (t >= NSEQ * (L_SEQ / 4)) return;
    int l4  = t % (L_SEQ / 4);
    int seq = t / (L_SEQ / 4);
    int b = seq / H_DIM;
    int h = seq % H_DIM;
    float w0 = enc_W[h];
    float w1 = enc_W[H_DIM + h];
    float bb = enc_b[h];
    float4 a = ((const float4*)(x + (b * D_IN + 0) * L_SEQ))[l4];
    float4 c = ((const float4*)(x + (b * D_IN + 1) * L_SEQ))[l4];
    float4 r;
    r.x = fmaf(w1, c.x, fmaf(w0, a.x, bb));
    r.y = fmaf(w1, c.y, fmaf(w0, a.y, bb));
    r.z = fmaf(w1, c.z, fmaf(w0, a.z, bb));
    r.w = fmaf(w1, c.w, fmaf(w0, a.w, bb));
    ((float4*)(g_h + seq * L_SEQ))[l4] = r;
}

// ---------------- pass 1: zero-init chunk-end states, chunks 0..CHUNKS-2 --------
__global__ void pass1_kernel(int layer) {
    int gid  = blockIdx.x * blockDim.x + threadIdx.x;
    int quarter = gid & 3;
    int pair = gid >> 2;
    int chunk = pair % (CHUNKS - 1);
    int seq   = pair / (CHUNKS - 1);
    int h = seq % H_DIM;

    const float* par = g_par + layer * 6 * H_DIM * NC;
    int S  = H_DIM * NC;
    int pb = h * NC + quarter * SPT;

    u64 wre2[NG], wim2[NG], nwim2[NG], sre2[NG], sim2[NG];
#pragma unroll
    for (int g = 0; g < NG; g++) {
        float2 wr = *(const float2*)(par + pb + 2 * g);
        float2 wi = *(const float2*)(par + S + pb + 2 * g);
        wre2[g]  = pk(wr.x, wr.y);
        wim2[g]  = pk(wi.x, wi.y);
        nwim2[g] = pk(-wi.x, -wi.y);
        sre2[g] = 0ull; sim2[g] = 0ull;
    }

    const float4* u4 = (const float4*)(g_h + seq * L_SEQ + chunk * CHLEN);
    for (int l = 0; l < CHLEN / 4; l++) {
        float4 u = u4[l];
        float uu[4] = {u.x, u.y, u.z, u.w};
#pragma unroll
        for (int q = 0; q < 4; q++) {
            u64 u2 = pk(uu[q], uu[q]);
#pragma unroll
            for (int g = 0; g < NG; g++) {
                u64 nr = fma2(nwim2[g], sim2[g], fma2(wre2[g], sre2[g], u2));
                u64 ni = fma2(wre2[g], sim2[g], mul2(wim2[g], sre2[g]));
                sre2[g] = nr; sim2[g] = ni;
            }
        }
    }

    float2* E = g_E + (seq * (CHUNKS - 1) + chunk) * NC + quarter * SPT;
#pragma unroll
    for (int g = 0; g < NG; g++) {
        float r0, r1, i0, i1;
        upk(sre2[g], r0, r1);
        upk(sim2[g], i0, i1);
        E[2 * g]     = make_float2(r0, i0);
        E[2 * g + 1] = make_float2(r1, i1);
    }
}

// ---------------- pass 2: exact recurrence + D skip + gelu -> g_y ----------------
// Epilogue restructured: butterfly transpose-reduce so lane q of each 4-lane
// group finishes element 4l+q alone (1 erff per 4 elements per lane, not 4).
__global__ void pass2_kernel(int layer, const float* __restrict__ Dvec) {
    int gid  = blockIdx.x * blockDim.x + threadIdx.x;
    int quarter = gid & 3;
    int rest = gid >> 2;
    int chunk = rest % CHUNKS;
    int seq   = rest / CHUNKS;
    int h = seq % H_DIM;

    const float* par = g_par + layer * 6 * H_DIM * NC;
    int S  = H_DIM * NC;
    int pb = h * NC + quarter * SPT;

    u64 sre2[NG], sim2[NG];
#pragma unroll
    for (int g = 0; g < NG; g++) { sre2[g] = 0ull; sim2[g] = 0ull; }

    if (chunk > 0) {
        u64 wpre2[NG], wpim2[NG], nwpim2[NG];
#pragma unroll
        for (int g = 0; g < NG; g++) {
            float2 wr = *(const float2*)(par + 4 * S + pb + 2 * g);
            float2 wi = *(const float2*)(par + 5 * S + pb + 2 * g);
            wpre2[g]  = pk(wr.x, wr.y);
            wpim2[g]  = pk(wi.x, wi.y);
            nwpim2[g] = pk(-wi.x, -wi.y);
        }
        for (int c = 0; c < chunk; c++) {
            const float2* E = g_E + (seq * (CHUNKS - 1) + c) * NC + quarter * SPT;
#pragma unroll
            for (int g = 0; g < NG; g++) {
                float2 e0 = E[2 * g], e1 = E[2 * g + 1];
                u64 re2 = pk(e0.x, e1.x);
                u64 im2 = pk(e0.y, e1.y);
                u64 nr = fma2(wpre2[g], sre2[g], fma2(nwpim2[g], sim2[g], re2));
                u64 ni = fma2(wpre2[g], sim2[g], fma2(wpim2[g], sre2[g], im2));
                sre2[g] = nr; sim2[g] = ni;
            }
        }
    }

    u64 wre2[NG], wim2[NG], nwim2[NG], cr2[NG], nci2[NG];
#pragma unroll
    for (int g = 0; g < NG; g++) {
        float2 wr = *(const float2*)(par + pb + 2 * g);
        float2 wi = *(const float2*)(par + S + pb + 2 * g);
        float2 cr = *(const float2*)(par + 2 * S + pb + 2 * g);
        float2 ci = *(const float2*)(par + 3 * S + pb + 2 * g);
        wre2[g]  = pk(wr.x, wr.y);
        wim2[g]  = pk(wi.x, wi.y);
        nwim2[g] = pk(-wi.x, -wi.y);
        cr2[g]   = pk(cr.x, cr.y);
        nci2[g]  = pk(-ci.x, -ci.y);
    }
    float Dh = Dvec[layer * H_DIM + h];

    const float4* u4 = (const float4*)(g_h + seq * L_SEQ + chunk * CHLEN);
    float*        yp = g_y + seq * L_SEQ + chunk * CHLEN;

    int  q1 = quarter & 1;
    bool q2 = (quarter & 2) != 0;

    for (int l = 0; l < CHLEN / 4; l++) {
        float4 u = u4[l];
        float uu[4] = {u.x, u.y, u.z, u.w};
        float s[4];
#pragma unroll
        for (int q = 0; q < 4; q++) {
            float uv = uu[q];
            u64 u2 = pk(uv, uv);
            u64 acc2 = 0ull;
#pragma unroll
            for (int g = 0; g < NG; g++) {
                u64 nr = fma2(nwim2[g], sim2[g], fma2(wre2[g], sre2[g], u2));
                u64 ni = fma2(wre2[g], sim2[g], mul2(wim2[g], sre2[g]));
                sre2[g] = nr; sim2[g] = ni;
                acc2 = fma2(cr2[g], nr, acc2);
                acc2 = fma2(nci2[g], ni, acc2);
            }
            float alo, ahi;
            upk(acc2, alo, ahi);
            s[q] = alo + ahi;
        }
        // butterfly transpose-reduce across the 4-lane group
        float sA = q1 ? s[1] : s[0];   // my element in low pair
        float sB = q1 ? s[0] : s[1];   // partner's element in low pair
        float sC = q1 ? s[3] : s[2];
        float sD = q1 ? s[2] : s[3];
        float p0 = sA + __shfl_xor_sync(0xffffffffu, sB, 1);
        float p1 = sC + __shfl_xor_sync(0xffffffffu, sD, 1);
        float send2 = q2 ? p0 : p1;
        float tot = (q2 ? p1 : p0) + __shfl_xor_sync(0xffffffffu, send2, 2);
        // my u value
        float ua = q1 ? uu[1] : uu[0];
        float ub = q1 ? uu[3] : uu[2];
        float um = q2 ? ub : ua;
        float yv = fmaf(um, Dh, tot);
        float gl = 0.5f * yv * (1.f + erff(yv * 0.7071067811865476f));
        yp[4 * l + quarter] = gl;
    }
}

// -------- GLU GEMM + residual + LayerNorm; GLT=32 l-tile, aliased smem ----------
// 256 threads: thread o owns output channel o (A for o<128, G for o>=128) over
// 32 l's -> 16 u64 accumulators. A-transpose overlays the dead y tile.
__global__ void __launch_bounds__(256) glu_kernel(int layer,
                           const float* __restrict__ out_b,
                           const float* __restrict__ ln_g,
                           const float* __restrict__ ln_b) {
    __shared__ float  ys[H_DIM][GLT];       // y tile [k][l]  16KB (reused as agA)
    __shared__ float  agG[GLT][H_DIM];      // gate transpose 16KB
    __shared__ float2 mv[GLT];

    float (*agA)[H_DIM] = (float(*)[H_DIM])ys;   // alias: A/z transpose [l][ch]

    int bl = blockIdx.x;
    int b  = bl / (L_SEQ / GLT);
    int l0 = (bl % (L_SEQ / GLT)) * GLT;
    int t  = threadIdx.x;                   // 256

    // stage y tile: 2 threads per row k, 16 floats each
    {
        int k = t >> 1, hf = t & 1;
        const float4* src = (const float4*)(g_y + (b * H_DIM + k) * L_SEQ + l0 + hf * 16);
        float4* dst = (float4*)&ys[k][hf * 16];
        dst[0] = __ldg(src);
        dst[1] = __ldg(src + 1);
        dst[2] = __ldg(src + 2);
        dst[3] = __ldg(src + 3);
    }
    __syncthreads();

    float bias = out_b[layer * 2 * H_DIM + t];
    u64 acc[16];
#pragma unroll
    for (int g = 0; g < 16; g++) acc[g] = pk(bias, bias);

    const float* wrow = g_Wt + layer * 2 * H_DIM * H_DIM + t;
#pragma unroll 2
    for (int k = 0; k < H_DIM; k++) {
        float w = __ldg(wrow + k * 2 * H_DIM);
        u64 w2 = pk(w, w);
        const ulonglong2* yr = (const ulonglong2*)&ys[k][0];
#pragma unroll
        for (int i = 0; i < 8; i++) {
            ulonglong2 q = yr[i];
            acc[2 * i]     = fma2(w2, q.x, acc[2 * i]);
            acc[2 * i + 1] = fma2(w2, q.y, acc[2 * i + 1]);
        }
    }
    __syncthreads();   // everyone done reading ys before A overlays it

    // scatter: A rows (t<128) into agA(=ys), G rows into agG
    {
        int ch = t & 127;
        if (t < 128) {
#pragma unroll
            for (int g = 0; g < 16; g++) {
                float v0, v1;
                upk(acc[g], v0, v1);
                agA[2 * g][ch]     = v0;
                agA[2 * g + 1][ch] = v1;
            }
        } else {
#pragma unroll
            for (int g = 0; g < 16; g++) {
                float v0, v1;
                upk(acc[g], v0, v1);
                agG[2 * g][ch]     = v0;
                agG[2 * g + 1][ch] = v1;
            }
        }
    }
    __syncthreads();

    // GLU + residual: thread handles ch = t&127, 16 l's selected by t>>7
    {
        int ch = t & 127, lh = t >> 7;
        const float4* hp = (const float4*)(g_h + (b * H_DIM + ch) * L_SEQ + l0 + lh * 16);
        float hv[16];
#pragma unroll
        for (int i = 0; i < 4; i++) ((float4*)hv)[i] = hp[i];
#pragma unroll
        for (int i = 0; i < 16; i++) {
            int l = lh * 16 + i;
            float a   = agA[l][ch];
            float gte = agG[l][ch];
            float sg  = 1.f / (1.f + expf(-gte));
            agA[l][ch] = fmaf(a, sg, hv[i]);    // z = GLU + residual (in place)
        }
    }
    __syncthreads();

    // LayerNorm stats per l (8 warps cover 32 l in 4 rounds)
    {
        int w = t >> 5, lane = t & 31;
#pragma unroll
        for (int l = w; l < GLT; l += 8) {
            float v0 = agA[l][lane],      v1 = agA[l][lane + 32];
            float v2 = agA[l][lane + 64], v3 = agA[l][lane + 96];
            float s = v0 + v1 + v2 + v3;
            float q = fmaf(v0, v0, fmaf(v1, v1, fmaf(v2, v2, v3 * v3)));
#pragma unroll
            for (int off = 16; off > 0; off >>= 1) {
                s += __shfl_xor_sync(0xffffffffu, s, off);
                q += __shfl_xor_sync(0xffffffffu, q, off);
            }
            if (lane == 0) {
                float m   = s * (1.0f / H_DIM);
                float var = q * (1.0f / H_DIM) - m * m;
                mv[l] = make_float2(m, rsqrtf(var + 1e-5f));
            }
        }
    }
    __syncthreads();

    // normalize + write back
    {
        int ch = t & 127, lh = t >> 7;
        float gam = ln_g[layer * H_DIM + ch];
        float bet = ln_b[layer * H_DIM + ch];
        float r[16];
#pragma unroll
        for (int i = 0; i < 16; i++) {
            int l = lh * 16 + i;
            float2 m = mv[l];
            r[i] = fmaf((agA[l][ch] - m.x) * m.y, gam, bet);
        }
        float4* wp = (float4*)(g_h + (b * H_DIM + ch) * L_SEQ + l0 + lh * 16);
#pragma unroll
        for (int i = 0; i < 4; i++) wp[i] = ((float4*)r)[i];
    }
}

// ---------------- mean over L ----------------
__global__ void pool_kernel() {
    int seq = blockIdx.x;
    int t   = threadIdx.x;    // 256 threads
    const float4* r = (const float4*)(g_h + seq * L_SEQ);
    float s = 0.f;
    for (int i = t; i < L_SEQ / 4; i += 256) {
        float4 v = r[i];
        s += v.x + v.y + v.z + v.w;
    }
    __shared__ float sm[256];
    sm[t] = s;
    __syncthreads();
    for (int off = 128; off > 0; off >>= 1) {
        if (t < off) sm[t] += sm[t + off];
        __syncthreads();
    }
    if (t == 0) g_pooled[seq] = sm[0] * (1.f / L_SEQ);
}

// ---------------- head ----------------
__global__ void head_kernel(const float* __restrict__ head_W,
                            const float* __restrict__ head_b,
                            float* __restrict__ out) {
    int t = threadIdx.x;
    if (t >= B_SZ * D_OUT) return;
    int b = t / D_OUT, o = t % D_OUT;
    float s = head_b[o];
    for (int h = 0; h < H_DIM; h++)
        s = fmaf(g_pooled[b * H_DIM + h], head_W[h * D_OUT + o], s);
    out[t] = s;
}

// ---------------- launch ----------------
extern "C" void kernel_launch(void* const* d_in, const int* in_sizes, int n_in,
                              void* d_out, int out_size) {
    const float* x          = (const float*)d_in[0];
    const float* enc_W      = (const float*)d_in[1];
    const float* enc_b      = (const float*)d_in[2];
    const float* log_dt     = (const float*)d_in[3];
    const float* C_re       = (const float*)d_in[4];
    const float* C_im       = (const float*)d_in[5];
    const float* log_A_real = (const float*)d_in[6];
    const float* A_imag     = (const float*)d_in[7];
    const float* Dvec       = (const float*)d_in[8];
    const float* out_W      = (const float*)d_in[9];
    const float* out_b      = (const float*)d_in[10];
    const float* ln_g       = (const float*)d_in[11];
    const float* ln_b       = (const float*)d_in[12];
    const float* head_W     = (const float*)d_in[13];
    const float* head_b     = (const float*)d_in[14];
    float* out = (float*)d_out;

    param_kernel<<<(NL * H_DIM * NC + 127) / 128, 128>>>(log_dt, C_re, C_im,
                                                         log_A_real, A_imag);
    wt_kernel<<<(NL * 2 * H_DIM * H_DIM + 255) / 256, 256>>>(out_W);
    enc_kernel<<<(NSEQ * (L_SEQ / 4)) / 256, 256>>>(x, enc_W, enc_b);

    for (int layer = 0; layer < NL; layer++) {
        pass1_kernel<<<(NSEQ * (CHUNKS - 1) * 4) / 128, 128>>>(layer);
        pass2_kernel<<<(NSEQ * CHUNKS * 4) / 128, 128>>>(layer, Dvec);
        glu_kernel<<<B_SZ * (L_SEQ / GLT), 256>>>(layer, out_b, ln_g, ln_b);
    }

    pool_kernel<<<NSEQ, 256>>>();
    head_kernel<<<1, 64>>>(head_W, head_b, out);
}